// round 1
// baseline (speedup 1.0000x reference)
#include <cuda_runtime.h>

// ChebyshevEncoder: x [B=16, N=65536, D=2] fp32 -> out [B, N, D*ORDER] fp32
// out[p*60 + d*30 + m] = T_m(x[p][d]) for pair p = b*N+n.
//
// Strategy: one thread per pair computes the 60 values into padded smem,
// then the block streams its contiguous 60*TPB-float output region with
// fully coalesced float4 stores. Kernel is pure-HBM-write-bound.

#define ORDER 30
#define TPB   128
#define PAD   61   // 60 padded to 61: gcd(61,32)=1 -> conflict-free smem writes

__global__ __launch_bounds__(TPB) void cheb_kernel(
    const float2* __restrict__ x,
    float4* __restrict__ out,
    int npairs)
{
    __shared__ float s[TPB * PAD];  // 31,232 bytes

    const int t = threadIdx.x;
    const int blockPair = blockIdx.x * TPB;
    const int p = blockPair + t;

    if (p < npairs) {
        const float2 xv = __ldg(&x[p]);
        float* row = &s[t * PAD];

        // d = 0
        {
            const float xx = xv.x;
            float tm1 = 1.0f;
            float tc  = xx;
            row[0] = tm1;
            row[1] = tc;
#pragma unroll
            for (int m = 2; m < ORDER; m++) {
                const float tn = 2.0f * xx * tc - tm1;
                row[m] = tn;
                tm1 = tc;
                tc = tn;
            }
        }
        // d = 1
        {
            const float xx = xv.y;
            float tm1 = 1.0f;
            float tc  = xx;
            row[ORDER + 0] = tm1;
            row[ORDER + 1] = tc;
#pragma unroll
            for (int m = 2; m < ORDER; m++) {
                const float tn = 2.0f * xx * tc - tm1;
                row[ORDER + m] = tn;
                tm1 = tc;
                tc = tn;
            }
        }
    }
    __syncthreads();

    // Block's output region: pairs [blockPair, blockPair+TPB) -> 60*TPB floats
    // = 15*TPB float4, fully contiguous starting at float4 index blockPair*15.
    const int base4  = blockPair * 15;          // global float4 index
    const int limit4 = npairs * 15;             // global float4 count
    const int total4 = TPB * 15;                // 1920 per full block

#pragma unroll
    for (int i = 0; i < 15; i++) {
        const int j = t + i * TPB;              // 0 .. 1919
        if (j < total4 && (base4 + j) < limit4) {
            const int e  = 4 * j;               // float offset within block region
            const int pl = e / 60;              // local pair
            const int k  = e % 60;              // offset within pair (multiple of 4)
            const float* r = &s[pl * PAD + k];
            out[base4 + j] = make_float4(r[0], r[1], r[2], r[3]);
        }
    }
}

extern "C" void kernel_launch(void* const* d_in, const int* in_sizes, int n_in,
                              void* d_out, int out_size)
{
    (void)n_in; (void)out_size;
    const float2* x = (const float2*)d_in[0];
    float4* out = (float4*)d_out;

    const int nelem  = in_sizes[0];      // B*N*D floats
    const int npairs = nelem / 2;        // B*N pairs (D=2)
    const int blocks = (npairs + TPB - 1) / TPB;

    cheb_kernel<<<blocks, TPB>>>(x, out, npairs);
}

// round 2
// speedup vs baseline: 1.0225x; 1.0225x over previous
#include <cuda_runtime.h>
#include <cstdint>

// ChebyshevEncoder: x [B=16, N=65536, D=2] fp32 -> out [B, N, D*ORDER] fp32
// out[p*60 + d*30 + m] = T_m(x[p][d]) for pair p = b*N+n.
//
// R2 strategy: one thread per pair computes all 60 values in registers,
// writes them to UNPADDED linear smem with conflict-free STS.128
// (quarter-warp scheduling: 15t mod 8 is a bijection over 8 consecutive
// lanes), then ONE cp.async.bulk.global.shared::cta per block streams the
// 30720B contiguous region smem->global via the TMA/bulk engine.
// This removes the LDS + STG phases from L1tex entirely.

#define ORDER 30
#define TPB   128
#define BYTES_PER_PAIR 240          // 60 floats
#define BLOCK_BYTES (TPB * BYTES_PER_PAIR)   // 30720

__device__ __forceinline__ uint32_t smem_u32(const void* p) {
    uint32_t a;
    asm("{ .reg .u64 t; cvta.to.shared.u64 t, %1; cvt.u32.u64 %0, t; }"
        : "=r"(a) : "l"(p));
    return a;
}

__global__ __launch_bounds__(TPB) void cheb_kernel(
    const float2* __restrict__ x,
    float* __restrict__ out,        // raw float pointer (global)
    int npairs)
{
    __shared__ __align__(16) float s[TPB * 60];   // 30720 B, exact output order

    const int t = threadIdx.x;
    const int blockPair = blockIdx.x * TPB;
    const int p = blockPair + t;

    if (p < npairs) {
        const float2 xv = __ldg(&x[p]);

        float T[60];
        // d = 0 -> T[0..29]
        {
            const float xx = xv.x;
            T[0] = 1.0f;
            T[1] = xx;
#pragma unroll
            for (int m = 2; m < ORDER; m++)
                T[m] = 2.0f * xx * T[m - 1] - T[m - 2];
        }
        // d = 1 -> T[30..59]
        {
            const float xx = xv.y;
            T[ORDER + 0] = 1.0f;
            T[ORDER + 1] = xx;
#pragma unroll
            for (int m = 2; m < ORDER; m++)
                T[ORDER + m] = 2.0f * xx * T[ORDER + m - 1] - T[ORDER + m - 2];
        }

        // 15 conflict-free STS.128 at float offset 60*t + 4*c (static indexing)
        float4* dst = reinterpret_cast<float4*>(&s[t * 60]);
        const float4* src = reinterpret_cast<const float4*>(T);
#pragma unroll
        for (int c = 0; c < 15; c++)
            dst[c] = src[c];
    }
    __syncthreads();

    if (t == 0) {
        // Pairs actually valid in this block (npairs = 8192*128 exactly in
        // the bench shape, but stay safe for tails; 240 is a multiple of 16).
        int cnt = npairs - blockPair;
        if (cnt > TPB) cnt = TPB;
        if (cnt > 0) {
            const uint32_t sbytes = (uint32_t)cnt * BYTES_PER_PAIR;
            const uint32_t saddr  = smem_u32(s);
            float* gdst = out + (size_t)blockPair * 60;

            // Order the generic-proxy STS writes before the async-proxy read.
            asm volatile("fence.proxy.async.shared::cta;" ::: "memory");
            asm volatile(
                "cp.async.bulk.global.shared::cta.bulk_group [%0], [%1], %2;"
                :: "l"(gdst), "r"(saddr), "r"(sbytes)
                : "memory");
            asm volatile("cp.async.bulk.commit_group;" ::: "memory");
            asm volatile("cp.async.bulk.wait_group 0;" ::: "memory");
        }
    }
}

extern "C" void kernel_launch(void* const* d_in, const int* in_sizes, int n_in,
                              void* d_out, int out_size)
{
    (void)n_in; (void)out_size;
    const float2* x = (const float2*)d_in[0];
    float* out = (float*)d_out;

    const int nelem  = in_sizes[0];      // B*N*D floats
    const int npairs = nelem / 2;        // B*N pairs (D=2)
    const int blocks = (npairs + TPB - 1) / TPB;

    cheb_kernel<<<blocks, TPB>>>(x, out, npairs);
}